// round 7
// baseline (speedup 1.0000x reference)
#include <cuda_runtime.h>
#include <cstdint>

#define BT_   8192
#define C_    1024
#define S_    4096
#define QH_   4
#define EPS_  1e-5f

// ---------------- scratch ----------------
__device__ float       g_xf[(size_t)BT_ * C_];        // LN output fp32
__device__ signed char g_q8[(size_t)BT_ * 4 * 512];   // [row][head][slice*256+d]
__device__ signed char g_k8[(size_t)S_ * 512];        // [s][slice*256+d]
__device__ signed char g_v8[2ull * 256 * S_];         // [slice][d][s]
__device__ unsigned int g_amax[3];

// ---------------- helpers ----------------
__device__ __forceinline__ uint32_t smem_u32(const void* p) {
    uint32_t a;
    asm("{ .reg .u64 t; cvta.to.shared.u64 t, %1; cvt.u32.u64 %0, t; }" : "=r"(a) : "l"(p));
    return a;
}
#define CPA16(saddr, gptr) \
    asm volatile("cp.async.cg.shared.global [%0], [%1], 16;" :: "r"(saddr), "l"(gptr))
#define CPCOMMIT() asm volatile("cp.async.commit_group;" ::: "memory")
#define CPWAIT(n)  asm volatile("cp.async.wait_group " #n ";" ::: "memory")

__device__ __forceinline__ void ldsm4(uint32_t* r, uint32_t addr) {
    asm volatile("ldmatrix.sync.aligned.m8n8.x4.shared.b16 {%0,%1,%2,%3}, [%4];"
                 : "=r"(r[0]), "=r"(r[1]), "=r"(r[2]), "=r"(r[3]) : "r"(addr));
}
__device__ __forceinline__ void mma_s8(int* c, const uint32_t* a, const uint32_t* b) {
    asm volatile("mma.sync.aligned.m16n8k32.row.col.s32.s8.s8.s32 "
                 "{%0,%1,%2,%3}, {%4,%5,%6,%7}, {%8,%9}, {%0,%1,%2,%3};"
                 : "+r"(c[0]), "+r"(c[1]), "+r"(c[2]), "+r"(c[3])
                 : "r"(a[0]), "r"(a[1]), "r"(a[2]), "r"(a[3]), "r"(b[0]), "r"(b[1]));
}
__device__ __forceinline__ int clamp127(int v) { return max(-127, min(127, v)); }

__global__ void init_kernel() { if (threadIdx.x < 3) g_amax[threadIdx.x] = 0u; }

// ---------------------------------------------------------------------------
__global__ void __launch_bounds__(256) ln_kernel(const float* __restrict__ res,
                                                 const float* __restrict__ gam,
                                                 const float* __restrict__ bet) {
    const int row = blockIdx.x;
    const float* x = res + (size_t)row * C_;
    float* y = g_xf + (size_t)row * C_;
    const int t = threadIdx.x;

    float v[4];
    float s = 0.f;
#pragma unroll
    for (int i = 0; i < 4; i++) { v[i] = x[t + 256 * i]; s += v[i]; }

    __shared__ float red[8];
    __shared__ float sh_mu, sh_rs;
#pragma unroll
    for (int o = 16; o; o >>= 1) s += __shfl_xor_sync(0xffffffffu, s, o);
    if ((t & 31) == 0) red[t >> 5] = s;
    __syncthreads();
    if (t == 0) {
        float tot = 0.f;
#pragma unroll
        for (int i = 0; i < 8; i++) tot += red[i];
        sh_mu = tot * (1.0f / (float)C_);
    }
    __syncthreads();
    const float mu = sh_mu;
    float s2 = 0.f;
#pragma unroll
    for (int i = 0; i < 4; i++) { float d = v[i] - mu; s2 += d * d; }
#pragma unroll
    for (int o = 16; o; o >>= 1) s2 += __shfl_xor_sync(0xffffffffu, s2, o);
    if ((t & 31) == 0) red[t >> 5] = s2;
    __syncthreads();
    if (t == 0) {
        float tot = 0.f;
#pragma unroll
        for (int i = 0; i < 8; i++) tot += red[i];
        sh_rs = rsqrtf(tot * (1.0f / (float)C_) + EPS_);
    }
    __syncthreads();
    const float rs = sh_rs;

    float amax = 0.f;
#pragma unroll
    for (int i = 0; i < 4; i++) {
        int c = t + 256 * i;
        float yy = (v[i] - mu) * rs * gam[c] + bet[c];
        y[c] = yy;
        amax = fmaxf(amax, fabsf(yy));
    }
#pragma unroll
    for (int o = 16; o; o >>= 1) amax = fmaxf(amax, __shfl_xor_sync(0xffffffffu, amax, o));
    __syncthreads();
    if ((t & 31) == 0) red[t >> 5] = amax;
    __syncthreads();
    if (t == 0) {
        float m = 0.f;
#pragma unroll
        for (int i = 0; i < 8; i++) m = fmaxf(m, red[i]);
        atomicMax(&g_amax[0], __float_as_uint(m));
    }
}

__global__ void __launch_bounds__(256) amax_kernel(const float* __restrict__ p,
                                                   int n, int slot) {
    float m = 0.f;
    for (int i = blockIdx.x * 256 + threadIdx.x; i < n; i += gridDim.x * 256)
        m = fmaxf(m, fabsf(p[i]));
#pragma unroll
    for (int o = 16; o; o >>= 1) m = fmaxf(m, __shfl_xor_sync(0xffffffffu, m, o));
    __shared__ float red[8];
    if ((threadIdx.x & 31) == 0) red[threadIdx.x >> 5] = m;
    __syncthreads();
    if (threadIdx.x == 0) {
        float mm = 0.f;
#pragma unroll
        for (int i = 0; i < 8; i++) mm = fmaxf(mm, red[i]);
        atomicMax(&g_amax[slot], __float_as_uint(mm));
    }
}

// ---------------------------------------------------------------------------
__global__ void __launch_bounds__(256) qext_kernel() {
    const int row = blockIdx.x, t = threadIdx.x;
    const float s1 = fmaxf(__uint_as_float(g_amax[0]), 1e-30f) * (1.f / 127.f);
    const float inv1 = 1.f / s1;
    float4 v = *(const float4*)(g_xf + (size_t)row * C_ + t * 4);
    int c = t * 4, head = c >> 8, d = c & 255;
    float vv[4] = {v.x, v.y, v.z, v.w};
    signed char o1[4], o2[4];
#pragma unroll
    for (int i = 0; i < 4; i++) {
        float f = vv[i] * inv1;
        int q1 = clamp127(__float2int_rn(f));
        int q2 = clamp127(__float2int_rn((f - (float)q1) * 256.f));
        o1[i] = (signed char)q1; o2[i] = (signed char)q2;
    }
    signed char* base = g_q8 + (((size_t)row * 4 + head) << 9) + d;
    *(char4*)(base)       = *(char4*)o1;
    *(char4*)(base + 256) = *(char4*)o2;
}

__global__ void __launch_bounds__(256) kext_kernel(const float* __restrict__ wfc) {
    int idx = blockIdx.x * 256 + threadIdx.x;
    const float s1 = fmaxf(__uint_as_float(g_amax[1]), 1e-30f) * (1.f / 127.f);
    float f = wfc[idx] * (1.f / s1);
    int q1 = clamp127(__float2int_rn(f));
    int q2 = clamp127(__float2int_rn((f - (float)q1) * 256.f));
    int s = idx >> 8, d = idx & 255;
    g_k8[(size_t)s * 512 + d]       = (signed char)q1;
    g_k8[(size_t)s * 512 + 256 + d] = (signed char)q2;
}

__global__ void __launch_bounds__(256) vext_kernel(const float* __restrict__ wproj) {
    int idx = blockIdx.x * 256 + threadIdx.x;
    const float s1 = fmaxf(__uint_as_float(g_amax[2]), 1e-30f) * (1.f / 127.f);
    float f = wproj[idx] * (1.f / s1);
    int q1 = clamp127(__float2int_rn(f));
    int q2 = clamp127(__float2int_rn((f - (float)q1) * 256.f));
    int r = idx >> 10, cc = idx & 1023;
    int d = r & 255;
    int s = cc * 4 + (r >> 8);
    g_v8[(size_t)d * 4096 + s]              = (signed char)q1;
    g_v8[1048576ull + (size_t)d * 4096 + s] = (signed char)q2;
}

// ---------------------------------------------------------------------------
// Fused kernel: CTA = 128 rows x 1 head; S chunks of 64, cp.async pipelined.
// GEMM1 warp tile: 16m x 64s (8x1). GEMM2 warp tile: 64m x 64d (2x4).
// int8 2-slice operands, 3 IMMA terms per GEMM; P requantized per row.
// SMEM: Q[128][528], K[64][528], P 2sl x [128][80], V 2sl x [256][80], scales[128].
// ---------------------------------------------------------------------------
#define SQ_OFF   0
#define SK_OFF   67584
#define SP_OFF   101376
#define SP_SL    10240
#define SV_OFF   121856
#define SV_SL    20480
#define SSC_OFF  162816
#define SMEM_TOT 163840

__global__ void __launch_bounds__(256, 1) fused_kernel(const float* __restrict__ res,
                                                       float* __restrict__ out) {
    extern __shared__ char smem[];
    const uint32_t sb = smem_u32(smem);

    const int t = threadIdx.x;
    const int lane = t & 31;
    const int wid = t >> 5;
    const int r = lane >> 2;        // 0..7
    const int u = lane & 3;         // 0..3
    const int head = blockIdx.y;
    const int row0 = blockIdx.x * 128;
    const int mh = wid & 1;         // GEMM2 m-half
    const int dq = wid >> 1;        // GEMM2 d-quarter

    const float s1q = fmaxf(__uint_as_float(g_amax[0]), 1e-30f) * (1.f / 127.f);
    const float s1k = fmaxf(__uint_as_float(g_amax[1]), 1e-30f) * (1.f / 127.f);
    const float s1v = fmaxf(__uint_as_float(g_amax[2]), 1e-30f) * (1.f / 127.f);
    const float Ssc = s1q * s1k;
    const float s1v7 = s1v * (1.f / 127.f);

    // ---- issue Q (group 1), K(0) (group 2) ----
#pragma unroll
    for (int i = 0; i < 16; i++) {
        int idx = i * 256 + t;
        int m = idx >> 5, c = idx & 31;
        CPA16(sb + SQ_OFF + m * 528 + c * 16,
              (const void*)(g_q8 + (((size_t)(row0 + m) * 4 + head) << 9) + c * 16));
    }
    CPCOMMIT();
#pragma unroll
    for (int i = 0; i < 8; i++) {
        int idx = i * 256 + t;
        int s = idx >> 5, c = idx & 31;
        CPA16(sb + SK_OFF + s * 528 + c * 16, (const void*)(g_k8 + ((size_t)s << 9) + c * 16));
    }
    CPCOMMIT();

    // ldmatrix lane addressing
    const uint32_t qa = sb + SQ_OFF + (uint32_t)((wid * 16 + (lane & 15)) * 528 + (lane >> 4) * 16);
    const int brow = (lane & 7) + ((lane >> 4) << 3);
    const int bc16 = ((lane >> 3) & 1) * 16;
    const uint32_t kb = sb + SK_OFF + (uint32_t)(brow * 528 + bc16);
    const uint32_t pa = sb + SP_OFF + (uint32_t)((mh * 64 + (lane & 15)) * 80 + (lane >> 4) * 16);
    const uint32_t vb = sb + SV_OFF + (uint32_t)((dq * 64 + brow) * 80 + bc16);
    float* scales = (float*)(smem + SSC_OFF);

    float c2[4][8][4];
#pragma unroll
    for (int a = 0; a < 4; a++)
#pragma unroll
        for (int b = 0; b < 8; b++)
#pragma unroll
            for (int e = 0; e < 4; e++) c2[a][b][e] = 0.f;

    for (int it = 0; it < 64; it++) {
        const int s0 = it * 64;

        // issue V(it)
#pragma unroll
        for (int i = 0; i < 8; i++) {
            int idx = i * 256 + t;
            int sl = idx >> 10;
            int rem = idx & 1023;
            int d = rem >> 2, c = rem & 3;
            CPA16(sb + SV_OFF + sl * SV_SL + d * 80 + c * 16,
                  (const void*)(g_v8 + (size_t)sl * 1048576ull + ((size_t)d << 12) + s0 + c * 16));
        }
        CPCOMMIT();
        CPWAIT(1);              // K(it) (and Q on it=0) ready
        __syncthreads();

        // ---- GEMM1: scores[16 x 64] per warp (rows wid*16..) ----
        float p[8][4];
#pragma unroll
        for (int hN = 0; hN < 2; hN++) {
            int acc[3][4][4];
#pragma unroll
            for (int a = 0; a < 3; a++)
#pragma unroll
                for (int b = 0; b < 4; b++)
#pragma unroll
                    for (int e = 0; e < 4; e++) acc[a][b][e] = 0;

#pragma unroll
            for (int ks = 0; ks < 8; ks++) {
                uint32_t A1[4], A2[4];
                ldsm4(A1, qa + ks * 32);
                ldsm4(A2, qa + 256 + ks * 32);
#pragma unroll
                for (int g2 = 0; g2 < 2; g2++) {
                    uint32_t B1[4], B2[4];
                    uint32_t ka = kb + (uint32_t)((hN * 32 + g2 * 16) * 528 + ks * 32);
                    ldsm4(B1, ka);
                    ldsm4(B2, ka + 256);
                    mma_s8(acc[0][g2 * 2 + 0], A1, B1);  mma_s8(acc[0][g2 * 2 + 1], A1, B1 + 2);
                    mma_s8(acc[1][g2 * 2 + 0], A1, B2);  mma_s8(acc[1][g2 * 2 + 1], A1, B2 + 2);
                    mma_s8(acc[2][g2 * 2 + 0], A2, B1);  mma_s8(acc[2][g2 * 2 + 1], A2, B1 + 2);
                }
            }
#pragma unroll
            for (int j = 0; j < 4; j++)
#pragma unroll
                for (int e = 0; e < 4; e++) {
                    float sc = Ssc * ((float)acc[0][j][e] +
                                      (float)(acc[1][j][e] + acc[2][j][e]) * (1.f / 256.f));
                    sc = fmaxf(sc, 0.f);
                    p[hN * 4 + j][e] = sc * sc;
                }
        }

        // per-row max (row r: e0,e1; row r+8: e2,e3)
        float mxa = 0.f, mxb = 0.f;
#pragma unroll
        for (int nt = 0; nt < 8; nt++) {
            mxa = fmaxf(mxa, fmaxf(p[nt][0], p[nt][1]));
            mxb = fmaxf(mxb, fmaxf(p[nt][2], p[nt][3]));
        }
        mxa = fmaxf(mxa, __shfl_xor_sync(0xffffffffu, mxa, 1));
        mxa = fmaxf(mxa, __shfl_xor_sync(0xffffffffu, mxa, 2));
        mxb = fmaxf(mxb, __shfl_xor_sync(0xffffffffu, mxb, 1));
        mxb = fmaxf(mxb, __shfl_xor_sync(0xffffffffu, mxb, 2));
        mxa = fmaxf(mxa, 1e-30f);
        mxb = fmaxf(mxb, 1e-30f);
        if (u == 0) {
            scales[wid * 16 + r]     = mxa;
            scales[wid * 16 + r + 8] = mxb;
        }
        const float inva = 127.f / mxa;
        const float invb = 127.f / mxb;

        // quantize P -> 2 int8 slices in smem
#pragma unroll
        for (int nt = 0; nt < 8; nt++) {
            float f0 = p[nt][0] * inva, f1 = p[nt][1] * inva;
            float f2 = p[nt][2] * invb, f3 = p[nt][3] * invb;
            int a10 = min(__float2int_rn(f0), 127);
            int a11 = min(__float2int_rn(f1), 127);
            int a12 = min(__float2int_rn(f2), 127);
            int a13 = min(__float2int_rn(f3), 127);
            int a20 = clamp127(__float2int_rn((f0 - (float)a10) * 256.f));
            int a21 = clamp127(__float2int_rn((f1 - (float)a11) * 256.f));
            int a22 = clamp127(__float2int_rn((f2 - (float)a12) * 256.f));
            int a23 = clamp127(__float2int_rn((f3 - (float)a13) * 256.f));
            int col = nt * 8 + 2 * u;
            int rowA = (wid * 16 + r) * 80 + col;
            int rowB = (wid * 16 + r + 8) * 80 + col;
            *(uint16_t*)(smem + SP_OFF + rowA)         = (uint16_t)((a10 & 255) | ((a11 & 255) << 8));
            *(uint16_t*)(smem + SP_OFF + rowB)         = (uint16_t)((a12 & 255) | ((a13 & 255) << 8));
            *(uint16_t*)(smem + SP_OFF + SP_SL + rowA) = (uint16_t)((a20 & 255) | ((a21 & 255) << 8));
            *(uint16_t*)(smem + SP_OFF + SP_SL + rowB) = (uint16_t)((a22 & 255) | ((a23 & 255) << 8));
        }
        __syncthreads();        // P + scales visible; K buffer free

        // issue K(it+1)
        if (it < 63) {
            const int sn = s0 + 64;
#pragma unroll
            for (int i = 0; i < 8; i++) {
                int idx = i * 256 + t;
                int s = idx >> 5, c = idx & 31;
                CPA16(sb + SK_OFF + s * 528 + c * 16,
                      (const void*)(g_k8 + ((size_t)(sn + s) << 9) + c * 16));
            }
            CPCOMMIT();
            CPWAIT(1);          // V(it) ready; K(it+1) pending
        } else {
            CPWAIT(0);
        }
        __syncthreads();

        // ---- GEMM2: O[128x256] += P . V^T ----
#pragma unroll
        for (int mt = 0; mt < 4; mt++) {
            const float w0 = scales[mh * 64 + mt * 16 + r] * s1v7;
            const float w1 = scales[mh * 64 + mt * 16 + r + 8] * s1v7;
            uint32_t P1[2][4], P2[2][4];
#pragma unroll
            for (int ks = 0; ks < 2; ks++) {
                ldsm4(P1[ks], pa + (uint32_t)(mt * 1280 + ks * 32));
                ldsm4(P2[ks], pa + (uint32_t)(SP_SL + mt * 1280 + ks * 32));
            }
#pragma unroll
            for (int h = 0; h < 4; h++) {
                int a0[2][4], a1[2][4], a2[2][4];
#pragma unroll
                for (int nt = 0; nt < 2; nt++)
#pragma unroll
                    for (int e = 0; e < 4; e++) { a0[nt][e] = 0; a1[nt][e] = 0; a2[nt][e] = 0; }
#pragma unroll
                for (int ks = 0; ks < 2; ks++) {
                    uint32_t V1[4], V2[4];
                    ldsm4(V1, vb + (uint32_t)(h * 1280 + ks * 32));
                    ldsm4(V2, vb + (uint32_t)(SV_SL + h * 1280 + ks * 32));
                    mma_s8(a0[0], P1[ks], V1);  mma_s8(a0[1], P1[ks], V1 + 2);
                    mma_s8(a1[0], P1[ks], V2);  mma_s8(a1[1], P1[ks], V2 + 2);
                    mma_s8(a2[0], P2[ks], V1);  mma_s8(a2[1], P2[ks], V1 + 2);
                }
#pragma unroll
                for (int nt = 0; nt < 2; nt++)
#pragma unroll
                    for (int e = 0; e < 4; e++) {
                        float val = (float)a0[nt][e] +
                                    (float)(a1[nt][e] + a2[nt][e]) * (1.f / 256.f);
                        c2[mt][2 * h + nt][e] += val * ((e < 2) ? w0 : w1);
                    }
            }
        }
        __syncthreads();        // V, P, scales free
    }

    // ---- epilogue: O + residual -> out ----
#pragma unroll
    for (int mt = 0; mt < 4; mt++) {
        const int rowA = row0 + mh * 64 + mt * 16 + r;
        const int rowB = rowA + 8;
        const float* rsA = res + (size_t)rowA * C_ + head * 256;
        const float* rsB = res + (size_t)rowB * C_ + head * 256;
        float* oA = out + (size_t)rowA * C_ + head * 256;
        float* oB = out + (size_t)rowB * C_ + head * 256;
#pragma unroll
        for (int j = 0; j < 8; j++) {
            const int col = dq * 64 + j * 8 + 2 * u;
            float2 a = *(const float2*)(rsA + col);
            float2 b = *(const float2*)(rsB + col);
            *(float2*)(oA + col) = make_float2(c2[mt][j][0] + a.x, c2[mt][j][1] + a.y);
            *(float2*)(oB + col) = make_float2(c2[mt][j][2] + b.x, c2[mt][j][3] + b.y);
        }
    }
}

// ---------------------------------------------------------------------------
extern "C" void kernel_launch(void* const* d_in, const int* in_sizes, int n_in,
                              void* d_out, int out_size) {
    (void)in_sizes; (void)n_in; (void)out_size;
    const float* residual = (const float*)d_in[0];
    const float* w_fc     = (const float*)d_in[1];
    const float* w_proj   = (const float*)d_in[2];
    const float* ln_g     = (const float*)d_in[3];
    const float* ln_b     = (const float*)d_in[4];
    float* out = (float*)d_out;

    cudaFuncSetAttribute(fused_kernel, cudaFuncAttributeMaxDynamicSharedMemorySize,
                         SMEM_TOT);

    init_kernel<<<1, 32>>>();
    ln_kernel<<<BT_, 256>>>(residual, ln_g, ln_b);
    amax_kernel<<<1024, 256>>>(w_fc, C_ * C_, 1);
    amax_kernel<<<1024, 256>>>(w_proj, C_ * C_, 2);
    qext_kernel<<<BT_, 256>>>();
    kext_kernel<<<4096, 256>>>(w_fc);
    vext_kernel<<<4096, 256>>>(w_proj);
    fused_kernel<<<dim3(64, QH_), 256, SMEM_TOT>>>(residual, out);
}

// round 8
// speedup vs baseline: 2.9467x; 2.9467x over previous
#include <cuda_runtime.h>
#include <cuda_bf16.h>
#include <cstdint>

#define BT_   8192
#define C_    1024
#define S_    4096
#define QH_   4
#define EPS_  1e-5f

// ---------------- scratch ----------------
__device__ __nv_bfloat16 g_q[(size_t)BT_ * 2048];   // 32MB [row][h*512 + (hi|lo)*256 + d]
__device__ __nv_bfloat16 g_k[(size_t)S_ * 512];     //  4MB [s][(hi|lo)*256 + d]
__device__ __nv_bfloat16 g_vt[2ull * 256 * S_];     //  4MB [hilo][d][s]

// ---------------- helpers ----------------
__device__ __forceinline__ uint32_t smem_u32(const void* p) {
    uint32_t a;
    asm("{ .reg .u64 t; cvta.to.shared.u64 t, %1; cvt.u32.u64 %0, t; }" : "=r"(a) : "l"(p));
    return a;
}
#define CPA16(saddr, gptr) \
    asm volatile("cp.async.cg.shared.global [%0], [%1], 16;" :: "r"(saddr), "l"(gptr))
#define CPCOMMIT() asm volatile("cp.async.commit_group;" ::: "memory")
#define CPWAIT(n)  asm volatile("cp.async.wait_group " #n ";" ::: "memory")

__device__ __forceinline__ void ldsm4(uint32_t* r, uint32_t addr) {
    asm volatile("ldmatrix.sync.aligned.m8n8.x4.shared.b16 {%0,%1,%2,%3}, [%4];"
                 : "=r"(r[0]), "=r"(r[1]), "=r"(r[2]), "=r"(r[3]) : "r"(addr));
}
__device__ __forceinline__ void mma16816(float* c, const uint32_t* a, const uint32_t* b) {
    asm volatile("mma.sync.aligned.m16n8k16.row.col.f32.bf16.bf16.f32 "
                 "{%0,%1,%2,%3}, {%4,%5,%6,%7}, {%8,%9}, {%0,%1,%2,%3};"
                 : "+f"(c[0]), "+f"(c[1]), "+f"(c[2]), "+f"(c[3])
                 : "r"(a[0]), "r"(a[1]), "r"(a[2]), "r"(a[3]), "r"(b[0]), "r"(b[1]));
}
// pack (f0 -> low half, f1 -> high half)
__device__ __forceinline__ uint32_t pack_bf2(float f0, float f1) {
    uint32_t d;
    asm("cvt.rn.bf16x2.f32 %0, %1, %2;" : "=r"(d) : "f"(f1), "f"(f0));
    return d;
}
__device__ __forceinline__ void bf16_split(float v, __nv_bfloat16& hi, __nv_bfloat16& lo) {
    hi = __float2bfloat16(v);
    lo = __float2bfloat16(v - __bfloat162float(hi));
}

// ---------------------------------------------------------------------------
// LayerNorm + bf16 split -> g_q
// ---------------------------------------------------------------------------
__global__ void __launch_bounds__(256) ln_kernel(const float* __restrict__ res,
                                                 const float* __restrict__ gam,
                                                 const float* __restrict__ bet) {
    const int row = blockIdx.x;
    const float* x = res + (size_t)row * C_;
    const int t = threadIdx.x;

    float v[4];
    float s = 0.f;
#pragma unroll
    for (int i = 0; i < 4; i++) { v[i] = x[t + 256 * i]; s += v[i]; }

    __shared__ float red[8];
    __shared__ float sh_mu, sh_rs;
#pragma unroll
    for (int o = 16; o; o >>= 1) s += __shfl_xor_sync(0xffffffffu, s, o);
    if ((t & 31) == 0) red[t >> 5] = s;
    __syncthreads();
    if (t == 0) {
        float tot = 0.f;
#pragma unroll
        for (int i = 0; i < 8; i++) tot += red[i];
        sh_mu = tot * (1.0f / (float)C_);
    }
    __syncthreads();
    const float mu = sh_mu;
    float s2 = 0.f;
#pragma unroll
    for (int i = 0; i < 4; i++) { float d = v[i] - mu; s2 += d * d; }
#pragma unroll
    for (int o = 16; o; o >>= 1) s2 += __shfl_xor_sync(0xffffffffu, s2, o);
    if ((t & 31) == 0) red[t >> 5] = s2;
    __syncthreads();
    if (t == 0) {
        float tot = 0.f;
#pragma unroll
        for (int i = 0; i < 8; i++) tot += red[i];
        sh_rs = rsqrtf(tot * (1.0f / (float)C_) + EPS_);
    }
    __syncthreads();
    const float rs = sh_rs;

#pragma unroll
    for (int i = 0; i < 4; i++) {
        int c = t + 256 * i;
        float y = (v[i] - mu) * rs * gam[c] + bet[c];
        int h = c >> 8, d = c & 255;
        __nv_bfloat16 hi, lo;
        bf16_split(y, hi, lo);
        size_t base = (size_t)row * 2048 + h * 512 + d;
        g_q[base] = hi;
        g_q[base + 256] = lo;
    }
}

__global__ void __launch_bounds__(256) kext_kernel(const float* __restrict__ wfc) {
    int idx = blockIdx.x * 256 + threadIdx.x;
    float v = wfc[idx];
    int s = idx >> 8, d = idx & 255;
    __nv_bfloat16 hi, lo;
    bf16_split(v, hi, lo);
    g_k[(size_t)s * 512 + d] = hi;
    g_k[(size_t)s * 512 + 256 + d] = lo;
}

__global__ void __launch_bounds__(256) vext_kernel(const float* __restrict__ wproj) {
    int idx = blockIdx.x * 256 + threadIdx.x;
    float v = wproj[idx];
    int r = idx >> 10, cc = idx & 1023;
    int d = r & 255;
    int s = cc * 4 + (r >> 8);
    __nv_bfloat16 hi, lo;
    bf16_split(v, hi, lo);
    g_vt[(size_t)d * 4096 + s] = hi;
    g_vt[1048576ull + (size_t)d * 4096 + s] = lo;
}

// ---------------------------------------------------------------------------
// Fused kernel: CTA = 128 rows x 1 head; S chunks of 32, cp.async pipelined.
// 3-barrier schedule: GEMM1 | sync | issueK,Pwrite,waitV | sync | GEMM2,waitK
// | sync | issueV.
// ---------------------------------------------------------------------------
#define SQ_OFF   0            // 128*1040   = 133120
#define SP_OFF   133120       // 2*128*80   = 20480
#define SP_LO    10240
#define SK_OFF   153600       // 32*1040    = 33280
#define SV_OFF   186880       // 2*256*80   = 40960
#define SV_LO    20480
#define SMEM_TOT 227840

__global__ void __launch_bounds__(256, 1) fused_kernel(const float* __restrict__ res,
                                                       float* __restrict__ out) {
    extern __shared__ char smem[];
    const uint32_t sb = smem_u32(smem);

    const int t = threadIdx.x;
    const int lane = t & 31;
    const int wid = t >> 5;
    const int r = lane >> 2;        // 0..7
    const int u = lane & 3;         // 0..3
    const int head = blockIdx.y;
    const int row0 = blockIdx.x * 128;

    // GEMM1 warp coords: 4 m-groups x 2 s-halves
    const int my = wid & 3;
    const int sx = wid >> 2;
    // GEMM2 warp coords: 2 m-halves x 4 d-quarters
    const int mh = wid & 1;
    const int dq = wid >> 1;

    // ---- issue Q (group), K(0) (group), V(0) (group) ----
#pragma unroll
    for (int i = 0; i < 32; i++) {
        int idx = i * 256 + t;
        int m = idx >> 6, c = idx & 63;
        CPA16(sb + SQ_OFF + m * 1040 + c * 16,
              (const void*)(g_q + (size_t)(row0 + m) * 2048 + head * 512 + c * 8));
    }
    CPCOMMIT();
#pragma unroll
    for (int i = 0; i < 8; i++) {
        int idx = i * 256 + t;
        int s = idx >> 6, c = idx & 63;
        CPA16(sb + SK_OFF + s * 1040 + c * 16,
              (const void*)(g_k + (size_t)s * 512 + c * 8));
    }
    CPCOMMIT();
#pragma unroll
    for (int i = 0; i < 8; i++) {
        int idx = i * 256 + t;
        int hilo = idx >> 10;
        int rem = idx & 1023;
        int d = rem >> 2, c = rem & 3;
        CPA16(sb + SV_OFF + hilo * SV_LO + d * 80 + c * 16,
              (const void*)(g_vt + (size_t)hilo * 1048576ull + (size_t)d * 4096 + c * 8));
    }
    CPCOMMIT();
    CPWAIT(1);              // Q + K(0) complete; V(0) pending
    __syncthreads();

    // ldmatrix lane addressing
    const uint32_t qa = sb + SQ_OFF + (uint32_t)((my * 32 + (lane & 15)) * 1040 + (lane >> 4) * 16);
    const int brow = (lane & 7) + ((lane >> 4) << 3);
    const int bc8  = ((lane >> 3) & 1) << 3;
    const uint32_t kb = sb + SK_OFF + (uint32_t)((sx * 16 + brow) * 1040 + bc8 * 2);
    const uint32_t pa = sb + SP_OFF + (uint32_t)((mh * 64 + (lane & 15)) * 80 + (lane >> 4) * 16);
    const uint32_t vb = sb + SV_OFF + (uint32_t)((dq * 64 + brow) * 80 + bc8 * 2);
    const uint32_t pw = sb + SP_OFF + (uint32_t)((my * 32 + r) * 80 + (sx * 16 + 2 * u) * 2);

    float c2[4][8][4];
#pragma unroll
    for (int a = 0; a < 4; a++)
#pragma unroll
        for (int b = 0; b < 8; b++)
#pragma unroll
            for (int e = 0; e < 4; e++) c2[a][b][e] = 0.f;

    for (int it = 0; it < 128; it++) {
        // ---- GEMM1: scores[128 x 32]  (K(it) visible) ----
        float c1[2][2][4];
#pragma unroll
        for (int a = 0; a < 2; a++)
#pragma unroll
            for (int b = 0; b < 2; b++)
#pragma unroll
                for (int e = 0; e < 4; e++) c1[a][b][e] = 0.f;

#pragma unroll 8
        for (int ks = 0; ks < 16; ks++) {
            uint32_t ah0[4], ah1[4], al0[4], al1[4], bh[4], bl[4];
            ldsm4(ah0, qa + ks * 32);
            ldsm4(ah1, qa + 16 * 1040 + ks * 32);
            ldsm4(al0, qa + 512 + ks * 32);
            ldsm4(al1, qa + 16 * 1040 + 512 + ks * 32);
            ldsm4(bh, kb + ks * 32);
            ldsm4(bl, kb + 512 + ks * 32);
            mma16816(c1[0][0], ah0, bh);  mma16816(c1[0][1], ah0, bh + 2);
            mma16816(c1[1][0], ah1, bh);  mma16816(c1[1][1], ah1, bh + 2);
            mma16816(c1[0][0], ah0, bl);  mma16816(c1[0][1], ah0, bl + 2);
            mma16816(c1[1][0], ah1, bl);  mma16816(c1[1][1], ah1, bl + 2);
            mma16816(c1[0][0], al0, bh);  mma16816(c1[0][1], al0, bh + 2);
            mma16816(c1[1][0], al1, bh);  mma16816(c1[1][1], al1, bh + 2);
        }
        __syncthreads();        // sync_a: all GEMM1 reads done -> K buffer free

        // issue K(it+1) (flies under P-conversion + GEMM2)
        if (it < 127) {
            const int sn = (it + 1) * 32;
#pragma unroll
            for (int i = 0; i < 8; i++) {
                int idx = i * 256 + t;
                int s = idx >> 6, c = idx & 63;
                CPA16(sb + SK_OFF + s * 1040 + c * 16,
                      (const void*)(g_k + (size_t)(sn + s) * 512 + c * 8));
            }
            CPCOMMIT();
        }

        // ---- relu^2 + split -> P smem (overlaps K load) ----
#pragma unroll
        for (int mt = 0; mt < 2; mt++) {
#pragma unroll
            for (int nt = 0; nt < 2; nt++) {
                uint32_t base = pw + (uint32_t)(mt * 16 * 80 + nt * 16);
#pragma unroll
                for (int half = 0; half < 2; half++) {
                    float p0 = fmaxf(c1[mt][nt][half * 2], 0.f);
                    float p1 = fmaxf(c1[mt][nt][half * 2 + 1], 0.f);
                    p0 *= p0; p1 *= p1;
                    uint32_t hh = pack_bf2(p0, p1);
                    float h0 = __uint_as_float(hh << 16);
                    float h1 = __uint_as_float(hh & 0xffff0000u);
                    uint32_t ll = pack_bf2(p0 - h0, p1 - h1);
                    uint32_t a = base + half * (8 * 80);
                    *(uint32_t*)(smem + (a - sb)) = hh;
                    *(uint32_t*)(smem + (a - sb) + SP_LO) = ll;
                }
            }
        }

        if (it < 127) { CPWAIT(1); } else { CPWAIT(0); }   // V(it) complete
        __syncthreads();        // sync_b: P + V visible to all warps

        // ---- GEMM2: O[128 x 256] += P . V^T ----
#pragma unroll
        for (int ks = 0; ks < 2; ks++) {
            uint32_t Ph[4][4], Pl[4][4];
#pragma unroll
            for (int mt = 0; mt < 4; mt++) {
                ldsm4(Ph[mt], pa + (uint32_t)(mt * 16 * 80 + ks * 32));
                ldsm4(Pl[mt], pa + (uint32_t)(SP_LO + mt * 16 * 80 + ks * 32));
            }
#pragma unroll
            for (int h = 0; h < 4; h++) {
                uint32_t vh[4], vl[4];
                ldsm4(vh, vb + (uint32_t)(h * 16 * 80 + ks * 32));
                ldsm4(vl, vb + (uint32_t)(SV_LO + h * 16 * 80 + ks * 32));
#pragma unroll
                for (int mt = 0; mt < 4; mt++) {
                    float* cA = c2[mt][2 * h];
                    float* cB = c2[mt][2 * h + 1];
                    mma16816(cA, Ph[mt], vh);  mma16816(cB, Ph[mt], vh + 2);
                    mma16816(cA, Ph[mt], vl);  mma16816(cB, Ph[mt], vl + 2);
                    mma16816(cA, Pl[mt], vh);  mma16816(cB, Pl[mt], vh + 2);
                }
            }
        }

        CPWAIT(0);              // K(it+1) complete (loaded under GEMM2)
        __syncthreads();        // sync_c: GEMM2 done -> V,P free; K visible

        // issue V(it+1)
        if (it < 127) {
            const int sv = (it + 1) * 32;
#pragma unroll
            for (int i = 0; i < 8; i++) {
                int idx = i * 256 + t;
                int hilo = idx >> 10;
                int rem = idx & 1023;
                int d = rem >> 2, c = rem & 3;
                CPA16(sb + SV_OFF + hilo * SV_LO + d * 80 + c * 16,
                      (const void*)(g_vt + (size_t)hilo * 1048576ull +
                                    (size_t)d * 4096 + sv + c * 8));
            }
            CPCOMMIT();
        }
    }

    // ---- epilogue: O + residual -> out ----
#pragma unroll
    for (int mt = 0; mt < 4; mt++) {
        const int rowA = row0 + mh * 64 + mt * 16 + r;
        const int rowB = rowA + 8;
        const float* rsA = res + (size_t)rowA * C_ + head * 256;
        const float* rsB = res + (size_t)rowB * C_ + head * 256;
        float* oA = out + (size_t)rowA * C_ + head * 256;
        float* oB = out + (size_t)rowB * C_ + head * 256;
#pragma unroll
        for (int j = 0; j < 8; j++) {
            const int col = dq * 64 + (j >> 1) * 16 + (j & 1) * 8 + 2 * u;
            float2 a = *(const float2*)(rsA + col);
            float2 b = *(const float2*)(rsB + col);
            *(float2*)(oA + col) = make_float2(c2[mt][j][0] + a.x, c2[mt][j][1] + a.y);
            *(float2*)(oB + col) = make_float2(c2[mt][j][2] + b.x, c2[mt][j][3] + b.y);
        }
    }
}

// ---------------------------------------------------------------------------
extern "C" void kernel_launch(void* const* d_in, const int* in_sizes, int n_in,
                              void* d_out, int out_size) {
    (void)in_sizes; (void)n_in; (void)out_size;
    const float* residual = (const float*)d_in[0];
    const float* w_fc     = (const float*)d_in[1];
    const float* w_proj   = (const float*)d_in[2];
    const float* ln_g     = (const float*)d_in[3];
    const float* ln_b     = (const float*)d_in[4];
    float* out = (float*)d_out;

    cudaFuncSetAttribute(fused_kernel, cudaFuncAttributeMaxDynamicSharedMemorySize,
                         SMEM_TOT);

    ln_kernel<<<BT_, 256>>>(residual, ln_g, ln_b);
    kext_kernel<<<4096, 256>>>(w_fc);
    vext_kernel<<<4096, 256>>>(w_proj);
    fused_kernel<<<dim3(64, QH_), 256, SMEM_TOT>>>(residual, out);
}

// round 9
// speedup vs baseline: 3.2239x; 1.0941x over previous
#include <cuda_runtime.h>
#include <cuda_bf16.h>
#include <cstdint>

#define BT_   8192
#define C_    1024
#define S_    4096
#define QH_   4
#define EPS_  1e-5f
#define NSPLIT 4
#define SSEG  1024            // S per split

// ---------------- scratch ----------------
__device__ __nv_bfloat16 g_q[(size_t)BT_ * 2048];   // 32MB [row][h*512 + (hi|lo)*256 + d]
__device__ __nv_bfloat16 g_k[(size_t)S_ * 512];     //  4MB [s][(hi|lo)*256 + d]
__device__ __nv_bfloat16 g_vt[2ull * 256 * S_];     //  4MB [hilo][d][s]
__device__ float g_part[(size_t)NSPLIT * BT_ * C_]; // 134MB partial outputs

// ---------------- helpers ----------------
__device__ __forceinline__ uint32_t smem_u32(const void* p) {
    uint32_t a;
    asm("{ .reg .u64 t; cvta.to.shared.u64 t, %1; cvt.u32.u64 %0, t; }" : "=r"(a) : "l"(p));
    return a;
}
#define CPA16(saddr, gptr) \
    asm volatile("cp.async.cg.shared.global [%0], [%1], 16;" :: "r"(saddr), "l"(gptr))
#define CPCOMMIT() asm volatile("cp.async.commit_group;" ::: "memory")
#define CPWAIT(n)  asm volatile("cp.async.wait_group " #n ";" ::: "memory")

__device__ __forceinline__ void ldsm4(uint32_t* r, uint32_t addr) {
    asm volatile("ldmatrix.sync.aligned.m8n8.x4.shared.b16 {%0,%1,%2,%3}, [%4];"
                 : "=r"(r[0]), "=r"(r[1]), "=r"(r[2]), "=r"(r[3]) : "r"(addr));
}
__device__ __forceinline__ void mma16816(float* c, const uint32_t* a, const uint32_t* b) {
    asm volatile("mma.sync.aligned.m16n8k16.row.col.f32.bf16.bf16.f32 "
                 "{%0,%1,%2,%3}, {%4,%5,%6,%7}, {%8,%9}, {%0,%1,%2,%3};"
                 : "+f"(c[0]), "+f"(c[1]), "+f"(c[2]), "+f"(c[3])
                 : "r"(a[0]), "r"(a[1]), "r"(a[2]), "r"(a[3]), "r"(b[0]), "r"(b[1]));
}
// pack (f0 -> low half, f1 -> high half)
__device__ __forceinline__ uint32_t pack_bf2(float f0, float f1) {
    uint32_t d;
    asm("cvt.rn.bf16x2.f32 %0, %1, %2;" : "=r"(d) : "f"(f1), "f"(f0));
    return d;
}
__device__ __forceinline__ void bf16_split(float v, __nv_bfloat16& hi, __nv_bfloat16& lo) {
    hi = __float2bfloat16(v);
    lo = __float2bfloat16(v - __bfloat162float(hi));
}

// ---------------------------------------------------------------------------
// LayerNorm + bf16 split -> g_q
// ---------------------------------------------------------------------------
__global__ void __launch_bounds__(256) ln_kernel(const float* __restrict__ res,
                                                 const float* __restrict__ gam,
                                                 const float* __restrict__ bet) {
    const int row = blockIdx.x;
    const float* x = res + (size_t)row * C_;
    const int t = threadIdx.x;

    float v[4];
    float s = 0.f;
#pragma unroll
    for (int i = 0; i < 4; i++) { v[i] = x[t + 256 * i]; s += v[i]; }

    __shared__ float red[8];
    __shared__ float sh_mu, sh_rs;
#pragma unroll
    for (int o = 16; o; o >>= 1) s += __shfl_xor_sync(0xffffffffu, s, o);
    if ((t & 31) == 0) red[t >> 5] = s;
    __syncthreads();
    if (t == 0) {
        float tot = 0.f;
#pragma unroll
        for (int i = 0; i < 8; i++) tot += red[i];
        sh_mu = tot * (1.0f / (float)C_);
    }
    __syncthreads();
    const float mu = sh_mu;
    float s2 = 0.f;
#pragma unroll
    for (int i = 0; i < 4; i++) { float d = v[i] - mu; s2 += d * d; }
#pragma unroll
    for (int o = 16; o; o >>= 1) s2 += __shfl_xor_sync(0xffffffffu, s2, o);
    if ((t & 31) == 0) red[t >> 5] = s2;
    __syncthreads();
    if (t == 0) {
        float tot = 0.f;
#pragma unroll
        for (int i = 0; i < 8; i++) tot += red[i];
        sh_rs = rsqrtf(tot * (1.0f / (float)C_) + EPS_);
    }
    __syncthreads();
    const float rs = sh_rs;

#pragma unroll
    for (int i = 0; i < 4; i++) {
        int c = t + 256 * i;
        float y = (v[i] - mu) * rs * gam[c] + bet[c];
        int h = c >> 8, d = c & 255;
        __nv_bfloat16 hi, lo;
        bf16_split(y, hi, lo);
        size_t base = (size_t)row * 2048 + h * 512 + d;
        g_q[base] = hi;
        g_q[base + 256] = lo;
    }
}

__global__ void __launch_bounds__(256) kext_kernel(const float* __restrict__ wfc) {
    int idx = blockIdx.x * 256 + threadIdx.x;
    float v = wfc[idx];
    int s = idx >> 8, d = idx & 255;
    __nv_bfloat16 hi, lo;
    bf16_split(v, hi, lo);
    g_k[(size_t)s * 512 + d] = hi;
    g_k[(size_t)s * 512 + 256 + d] = lo;
}

__global__ void __launch_bounds__(256) vext_kernel(const float* __restrict__ wproj) {
    int idx = blockIdx.x * 256 + threadIdx.x;
    float v = wproj[idx];
    int r = idx >> 10, cc = idx & 1023;
    int d = r & 255;
    int s = cc * 4 + (r >> 8);
    __nv_bfloat16 hi, lo;
    bf16_split(v, hi, lo);
    g_vt[(size_t)d * 4096 + s] = hi;
    g_vt[1048576ull + (size_t)d * 4096 + s] = lo;
}

// ---------------------------------------------------------------------------
// Reduce: out = residual + sum of 4 partials
// ---------------------------------------------------------------------------
__global__ void __launch_bounds__(256) reduce_kernel(const float* __restrict__ res,
                                                     float* __restrict__ out) {
    const size_t i = ((size_t)blockIdx.x * 256 + threadIdx.x) * 4;
    float4 a = *(const float4*)(res + i);
    float4 p0 = *(const float4*)(g_part + i);
    float4 p1 = *(const float4*)(g_part + (size_t)BT_ * C_ + i);
    float4 p2 = *(const float4*)(g_part + 2ull * BT_ * C_ + i);
    float4 p3 = *(const float4*)(g_part + 3ull * BT_ * C_ + i);
    float4 o;
    o.x = a.x + (p0.x + p1.x) + (p2.x + p3.x);
    o.y = a.y + (p0.y + p1.y) + (p2.y + p3.y);
    o.z = a.z + (p0.z + p1.z) + (p2.z + p3.z);
    o.w = a.w + (p0.w + p1.w) + (p2.w + p3.w);
    *(float4*)(out + i) = o;
}

// ---------------------------------------------------------------------------
// Fused kernel: CTA = 128 rows x 1 head x 1 S-split(1024); chunks of 32.
// ---------------------------------------------------------------------------
#define SQ_OFF   0            // 128*1040   = 133120
#define SP_OFF   133120       // 2*128*80   = 20480
#define SP_LO    10240
#define SK_OFF   153600       // 32*1040    = 33280
#define SV_OFF   186880       // 2*256*80   = 40960
#define SV_LO    20480
#define SMEM_TOT 227840
#define NIT      (SSEG / 32)  // 32 chunks per split

__global__ void __launch_bounds__(256, 1) fused_kernel() {
    extern __shared__ char smem[];
    const uint32_t sb = smem_u32(smem);

    const int t = threadIdx.x;
    const int lane = t & 31;
    const int wid = t >> 5;
    const int r = lane >> 2;        // 0..7
    const int u = lane & 3;         // 0..3
    const int head = blockIdx.y;
    const int row0 = blockIdx.x * 128;
    const int sBase = blockIdx.z * SSEG;

    // GEMM1 warp coords: 4 m-groups x 2 s-halves
    const int my = wid & 3;
    const int sx = wid >> 2;
    // GEMM2 warp coords: 2 m-halves x 4 d-quarters
    const int mh = wid & 1;
    const int dq = wid >> 1;

    // ---- issue Q (group), K(0) (group), V(0) (group) ----
#pragma unroll
    for (int i = 0; i < 32; i++) {
        int idx = i * 256 + t;
        int m = idx >> 6, c = idx & 63;
        CPA16(sb + SQ_OFF + m * 1040 + c * 16,
              (const void*)(g_q + (size_t)(row0 + m) * 2048 + head * 512 + c * 8));
    }
    CPCOMMIT();
#pragma unroll
    for (int i = 0; i < 8; i++) {
        int idx = i * 256 + t;
        int s = idx >> 6, c = idx & 63;
        CPA16(sb + SK_OFF + s * 1040 + c * 16,
              (const void*)(g_k + (size_t)(sBase + s) * 512 + c * 8));
    }
    CPCOMMIT();
#pragma unroll
    for (int i = 0; i < 8; i++) {
        int idx = i * 256 + t;
        int hilo = idx >> 10;
        int rem = idx & 1023;
        int d = rem >> 2, c = rem & 3;
        CPA16(sb + SV_OFF + hilo * SV_LO + d * 80 + c * 16,
              (const void*)(g_vt + (size_t)hilo * 1048576ull + (size_t)d * 4096 + sBase + c * 8));
    }
    CPCOMMIT();
    CPWAIT(1);              // Q + K(0) complete; V(0) pending
    __syncthreads();

    // ldmatrix lane addressing
    const uint32_t qa = sb + SQ_OFF + (uint32_t)((my * 32 + (lane & 15)) * 1040 + (lane >> 4) * 16);
    const int brow = (lane & 7) + ((lane >> 4) << 3);
    const int bc8  = ((lane >> 3) & 1) << 3;
    const uint32_t kb = sb + SK_OFF + (uint32_t)((sx * 16 + brow) * 1040 + bc8 * 2);
    const uint32_t pa = sb + SP_OFF + (uint32_t)((mh * 64 + (lane & 15)) * 80 + (lane >> 4) * 16);
    const uint32_t vb = sb + SV_OFF + (uint32_t)((dq * 64 + brow) * 80 + bc8 * 2);
    const uint32_t pw = sb + SP_OFF + (uint32_t)((my * 32 + r) * 80 + (sx * 16 + 2 * u) * 2);

    float c2[4][8][4];
#pragma unroll
    for (int a = 0; a < 4; a++)
#pragma unroll
        for (int b = 0; b < 8; b++)
#pragma unroll
            for (int e = 0; e < 4; e++) c2[a][b][e] = 0.f;

    for (int it = 0; it < NIT; it++) {
        // ---- GEMM1: scores[128 x 32]  (K(it) visible) ----
        float c1[2][2][4];
#pragma unroll
        for (int a = 0; a < 2; a++)
#pragma unroll
            for (int b = 0; b < 2; b++)
#pragma unroll
                for (int e = 0; e < 4; e++) c1[a][b][e] = 0.f;

#pragma unroll 8
        for (int ks = 0; ks < 16; ks++) {
            uint32_t ah0[4], ah1[4], al0[4], al1[4], bh[4], bl[4];
            ldsm4(ah0, qa + ks * 32);
            ldsm4(ah1, qa + 16 * 1040 + ks * 32);
            ldsm4(al0, qa + 512 + ks * 32);
            ldsm4(al1, qa + 16 * 1040 + 512 + ks * 32);
            ldsm4(bh, kb + ks * 32);
            ldsm4(bl, kb + 512 + ks * 32);
            mma16816(c1[0][0], ah0, bh);  mma16816(c1[0][1], ah0, bh + 2);
            mma16816(c1[1][0], ah1, bh);  mma16816(c1[1][1], ah1, bh + 2);
            mma16816(c1[0][0], ah0, bl);  mma16816(c1[0][1], ah0, bl + 2);
            mma16816(c1[1][0], ah1, bl);  mma16816(c1[1][1], ah1, bl + 2);
            mma16816(c1[0][0], al0, bh);  mma16816(c1[0][1], al0, bh + 2);
            mma16816(c1[1][0], al1, bh);  mma16816(c1[1][1], al1, bh + 2);
        }
        __syncthreads();        // sync_a: K buffer free

        // issue K(it+1)
        if (it < NIT - 1) {
            const int sn = sBase + (it + 1) * 32;
#pragma unroll
            for (int i = 0; i < 8; i++) {
                int idx = i * 256 + t;
                int s = idx >> 6, c = idx & 63;
                CPA16(sb + SK_OFF + s * 1040 + c * 16,
                      (const void*)(g_k + (size_t)(sn + s) * 512 + c * 8));
            }
            CPCOMMIT();
        }

        // ---- relu^2 + split -> P smem (overlaps K load) ----
#pragma unroll
        for (int mt = 0; mt < 2; mt++) {
#pragma unroll
            for (int nt = 0; nt < 2; nt++) {
                uint32_t base = pw + (uint32_t)(mt * 16 * 80 + nt * 16);
#pragma unroll
                for (int half = 0; half < 2; half++) {
                    float p0 = fmaxf(c1[mt][nt][half * 2], 0.f);
                    float p1 = fmaxf(c1[mt][nt][half * 2 + 1], 0.f);
                    p0 *= p0; p1 *= p1;
                    uint32_t hh = pack_bf2(p0, p1);
                    float h0 = __uint_as_float(hh << 16);
                    float h1 = __uint_as_float(hh & 0xffff0000u);
                    uint32_t ll = pack_bf2(p0 - h0, p1 - h1);
                    uint32_t a = base + half * (8 * 80);
                    *(uint32_t*)(smem + (a - sb)) = hh;
                    *(uint32_t*)(smem + (a - sb) + SP_LO) = ll;
                }
            }
        }

        if (it < NIT - 1) { CPWAIT(1); } else { CPWAIT(0); }   // V(it) complete
        __syncthreads();        // sync_b: P + V visible

        // ---- GEMM2: O[128 x 256] += P . V^T ----
#pragma unroll
        for (int ks = 0; ks < 2; ks++) {
            uint32_t Ph[4][4], Pl[4][4];
#pragma unroll
            for (int mt = 0; mt < 4; mt++) {
                ldsm4(Ph[mt], pa + (uint32_t)(mt * 16 * 80 + ks * 32));
                ldsm4(Pl[mt], pa + (uint32_t)(SP_LO + mt * 16 * 80 + ks * 32));
            }
#pragma unroll
            for (int h = 0; h < 4; h++) {
                uint32_t vh[4], vl[4];
                ldsm4(vh, vb + (uint32_t)(h * 16 * 80 + ks * 32));
                ldsm4(vl, vb + (uint32_t)(SV_LO + h * 16 * 80 + ks * 32));
#pragma unroll
                for (int mt = 0; mt < 4; mt++) {
                    float* cA = c2[mt][2 * h];
                    float* cB = c2[mt][2 * h + 1];
                    mma16816(cA, Ph[mt], vh);  mma16816(cB, Ph[mt], vh + 2);
                    mma16816(cA, Ph[mt], vl);  mma16816(cB, Ph[mt], vl + 2);
                    mma16816(cA, Pl[mt], vh);  mma16816(cB, Pl[mt], vh + 2);
                }
            }
        }

        CPWAIT(0);              // K(it+1) complete
        __syncthreads();        // sync_c: V,P free; K visible

        // issue V(it+1)
        if (it < NIT - 1) {
            const int sv = sBase + (it + 1) * 32;
#pragma unroll
            for (int i = 0; i < 8; i++) {
                int idx = i * 256 + t;
                int hilo = idx >> 10;
                int rem = idx & 1023;
                int d = rem >> 2, c = rem & 3;
                CPA16(sb + SV_OFF + hilo * SV_LO + d * 80 + c * 16,
                      (const void*)(g_vt + (size_t)hilo * 1048576ull +
                                    (size_t)d * 4096 + sv + c * 8));
            }
            CPCOMMIT();
        }
    }

    // ---- epilogue: write partial O (no residual) ----
    float* po = g_part + (size_t)blockIdx.z * BT_ * C_;
#pragma unroll
    for (int mt = 0; mt < 4; mt++) {
        const int rowA = row0 + mh * 64 + mt * 16 + r;
        const int rowB = rowA + 8;
        float* oA = po + (size_t)rowA * C_ + head * 256;
        float* oB = po + (size_t)rowB * C_ + head * 256;
#pragma unroll
        for (int j = 0; j < 8; j++) {
            const int col = dq * 64 + (j >> 1) * 16 + (j & 1) * 8 + 2 * u;
            *(float2*)(oA + col) = make_float2(c2[mt][j][0], c2[mt][j][1]);
            *(float2*)(oB + col) = make_float2(c2[mt][j][2], c2[mt][j][3]);
        }
    }
}

// ---------------------------------------------------------------------------
extern "C" void kernel_launch(void* const* d_in, const int* in_sizes, int n_in,
                              void* d_out, int out_size) {
    (void)in_sizes; (void)n_in; (void)out_size;
    const float* residual = (const float*)d_in[0];
    const float* w_fc     = (const float*)d_in[1];
    const float* w_proj   = (const float*)d_in[2];
    const float* ln_g     = (const float*)d_in[3];
    const float* ln_b     = (const float*)d_in[4];
    float* out = (float*)d_out;

    cudaFuncSetAttribute(fused_kernel, cudaFuncAttributeMaxDynamicSharedMemorySize,
                         SMEM_TOT);

    ln_kernel<<<BT_, 256>>>(residual, ln_g, ln_b);
    kext_kernel<<<4096, 256>>>(w_fc);
    vext_kernel<<<4096, 256>>>(w_proj);
    fused_kernel<<<dim3(64, QH_, NSPLIT), 256, SMEM_TOT>>>();
    reduce_kernel<<<BT_ * C_ / 1024, 256>>>(residual, out);
}